// round 16
// baseline (speedup 1.0000x reference)
#include <cuda_runtime.h>
#include <cuda_fp16.h>
#include <math_constants.h>
#include <stdint.h>

// Problem constants
#define B_   2
#define T_   2048
#define D_   2048
#define H_   16
#define HKV_ 4
#define HD_  128
#define G_   (H_ / HKV_)      // 4
#define M_   (B_ * T_)        // 4096
#define KVD_ (HKV_ * HD_)     // 512
#define QKVN_ (D_ + 2 * KVD_) // 3072 (combined Q|K|V output width)

// ---------------------------------------------------------------------------
// Scratch (device globals; no allocation allowed) — all fp16
// ---------------------------------------------------------------------------
__device__ __half g_xh[(size_t)M_ * D_];        // 16 MB
__device__ __half g_wqkvh[(size_t)QKVN_ * D_];  // 12 MB
__device__ __half g_woh[(size_t)D_ * D_];       //  8 MB
__device__ __half g_qkv[(size_t)M_ * QKVN_];    // 24 MB (Q 0-2047 | K 2048-2559 | V 2560-3071)
__device__ __half g_attn[(size_t)M_ * D_];      // 16 MB

// ---------------------------------------------------------------------------
// Helpers
// ---------------------------------------------------------------------------
__device__ __forceinline__ uint32_t pk_h2(float lo, float hi) {
    half2 h = __floats2half2_rn(lo, hi);
    return *(uint32_t*)&h;
}

__device__ __forceinline__ uint32_t smem_u32(const void* p) {
    uint32_t a;
    asm("{ .reg .u64 t; cvta.to.shared.u64 t, %1; cvt.u32.u64 %0, t; }"
        : "=r"(a) : "l"(p));
    return a;
}

__device__ __forceinline__ uint32_t exp2_pair(float lo, float hi, half2 mh) {
    half2 v = h2exp2(__hsub2(__floats2half2_rn(lo, hi), mh));
    return *(uint32_t*)&v;
}

#define MMA_F16(c, a, b)                                                      \
    asm volatile(                                                             \
        "mma.sync.aligned.m16n8k16.row.col.f32.f16.f16.f32 "                  \
        "{%0,%1,%2,%3},{%4,%5,%6,%7},{%8,%9},{%0,%1,%2,%3};"                  \
        : "+f"((c)[0]), "+f"((c)[1]), "+f"((c)[2]), "+f"((c)[3])              \
        : "r"((a)[0]), "r"((a)[1]), "r"((a)[2]), "r"((a)[3]),                 \
          "r"((b)[0]), "r"((b)[1]))

#define LDSM_X4(r0, r1, r2, r3, addr)                                         \
    asm volatile(                                                             \
        "ldmatrix.sync.aligned.m8n8.x4.shared.b16 {%0,%1,%2,%3}, [%4];"       \
        : "=r"(r0), "=r"(r1), "=r"(r2), "=r"(r3) : "r"(addr))

#define LDSM_X4_T(r0, r1, r2, r3, addr)                                       \
    asm volatile(                                                             \
        "ldmatrix.sync.aligned.m8n8.x4.trans.shared.b16 {%0,%1,%2,%3}, [%4];" \
        : "=r"(r0), "=r"(r1), "=r"(r2), "=r"(r3) : "r"(addr))

#define CP_ASYNC16(dst, src)                                                  \
    asm volatile("cp.async.cg.shared.global [%0], [%1], 16;"                  \
                 :: "r"(dst), "l"(src))
#define CP_COMMIT() asm volatile("cp.async.commit_group;" ::: "memory")
#define CP_WAIT0()  asm volatile("cp.async.wait_group 0;" ::: "memory")
#define CP_WAIT1()  asm volatile("cp.async.wait_group 1;" ::: "memory")

// ---------------------------------------------------------------------------
// Fused fp32->fp16 conversion: x | Wq | Wk | Wv | Wo in one launch.
// ---------------------------------------------------------------------------
#define XB_   (M_ * D_ / 2048)        // 4096 blocks
#define WQB_  (D_ * D_ / 2048)        // 2048
#define WKB_  (KVD_ * D_ / 2048)      // 512
#define WVB_  (KVD_ * D_ / 2048)      // 512
#define WOB_  (D_ * D_ / 2048)        // 2048
#define F2H_BLOCKS (XB_ + WQB_ + WKB_ + WVB_ + WOB_)   // 9216

__global__ __launch_bounds__(256) void f2h_all_kernel(
    const float* __restrict__ x,  const float* __restrict__ Wq,
    const float* __restrict__ Wk, const float* __restrict__ Wv,
    const float* __restrict__ Wo,
    __half* __restrict__ xh, __half* __restrict__ wqkvh,
    __half* __restrict__ woh)
{
    int blk = blockIdx.x;
    const float* src;
    __half* dst;
    if (blk < XB_)                     { src = x;  dst = xh;    }
    else if ((blk -= XB_)  < WQB_)     { src = Wq; dst = wqkvh; }
    else if ((blk -= WQB_) < WKB_)     { src = Wk; dst = wqkvh + (size_t)D_ * D_; }
    else if ((blk -= WKB_) < WVB_)     { src = Wv; dst = wqkvh + (size_t)(D_ + KVD_) * D_; }
    else { blk -= WVB_;                  src = Wo; dst = woh;   }

    size_t i = ((size_t)blk * 256 + threadIdx.x) * 8;
    float4 a = *(const float4*)(src + i);
    float4 b = *(const float4*)(src + i + 4);
    uint4 o = { pk_h2(a.x, a.y), pk_h2(a.z, a.w),
                pk_h2(b.x, b.y), pk_h2(b.z, b.w) };
    *(uint4*)(dst + i) = o;
}

// ---------------------------------------------------------------------------
// fp16 tensor-core GEMM, 3-stage cp.async pipeline (unchanged).
// ---------------------------------------------------------------------------
#define HSTRIDE 20
#define HROW_BYTES (HSTRIDE * 4)                 // 80
#define HTILE_WORDS (128 * HSTRIDE)              // 2560 u32 per tile
#define HTILE_BYTES (HTILE_WORDS * 4)            // 10240
#define GEMM_SMEM_BYTES (6 * HTILE_BYTES)        // 61440 B

__global__ __launch_bounds__(256) void gemm_nt_h_kernel(
    const __half* __restrict__ A, const __half* __restrict__ Bm,
    __half* __restrict__ Ch, float* __restrict__ Cf, int M, int N, int K)
{
    extern __shared__ uint32_t smw[];
    const uint32_t smBase = smem_u32(smw);

    const int tid  = threadIdx.x;
    const int lane = tid & 31;
    const int warp = tid >> 5;
    const int row0 = blockIdx.y * 128;
    const int col0 = blockIdx.x * 128;
    const int wm   = (warp >> 2) * 64;
    const int wn   = (warp & 3) * 32;
    const int lk   = lane & 3;
    const int lr   = lane >> 2;

    const uint32_t aoff = (uint32_t)(lane & 15) * HROW_BYTES + (uint32_t)(lane >> 4) * 16;
    const uint32_t boff = ((uint32_t)((lane >> 4) * 8 + (lane & 7))) * HROW_BYTES
                        + (uint32_t)((lane >> 3) & 1) * 16;

    int mL[2], hcL[2];
    uint32_t stA[2], stB[2];
#pragma unroll
    for (int t = 0; t < 2; t++) {
        int idx = tid + 256 * t;
        mL[t]  = idx >> 2;
        hcL[t] = (idx & 3) << 3;
        uint32_t wb = (uint32_t)(mL[t] * HSTRIDE + ((idx & 3) << 2)) * 4;
        stA[t] = smBase + wb;
        stB[t] = smBase + 3 * HTILE_BYTES + wb;
    }

    float c[4][4][4];
#pragma unroll
    for (int mi = 0; mi < 4; mi++)
#pragma unroll
        for (int ni = 0; ni < 4; ni++)
#pragma unroll
            for (int r = 0; r < 4; r++) c[mi][ni][r] = 0.f;

    const int niter = K >> 5;

#pragma unroll
    for (int st = 0; st < 2; st++) {
        const int k0 = st << 5;
        const uint32_t bo = (uint32_t)st * HTILE_BYTES;
#pragma unroll
        for (int t = 0; t < 2; t++) {
            CP_ASYNC16(stA[t] + bo, &A [(size_t)(row0 + mL[t]) * K + k0 + hcL[t]]);
            CP_ASYNC16(stB[t] + bo, &Bm[(size_t)(col0 + mL[t]) * K + k0 + hcL[t]]);
        }
        CP_COMMIT();
    }

    int buf = 0;
    for (int it = 0; it < niter; ++it) {
        CP_WAIT1();
        __syncthreads();

        if (it + 2 < niter) {
            int nb = buf + 2; if (nb >= 3) nb -= 3;
            const int k0 = (it + 2) << 5;
            const uint32_t bo = (uint32_t)nb * HTILE_BYTES;
#pragma unroll
            for (int t = 0; t < 2; t++) {
                CP_ASYNC16(stA[t] + bo, &A [(size_t)(row0 + mL[t]) * K + k0 + hcL[t]]);
                CP_ASYNC16(stB[t] + bo, &Bm[(size_t)(col0 + mL[t]) * K + k0 + hcL[t]]);
            }
            CP_COMMIT();
        }

        const uint32_t aB = smBase + (uint32_t)buf * HTILE_BYTES + aoff;
        const uint32_t bB = smBase + (uint32_t)(3 + buf) * HTILE_BYTES + boff;
#pragma unroll
        for (int s = 0; s < 2; s++) {
            const uint32_t so = (uint32_t)s * 32;
            uint32_t af[4][4], bf[4][2];
#pragma unroll
            for (int mi = 0; mi < 4; mi++)
                LDSM_X4(af[mi][0], af[mi][1], af[mi][2], af[mi][3],
                        aB + (uint32_t)(wm + 16 * mi) * HROW_BYTES + so);
#pragma unroll
            for (int p = 0; p < 2; p++)
                LDSM_X4(bf[2 * p][0], bf[2 * p][1], bf[2 * p + 1][0], bf[2 * p + 1][1],
                        bB + (uint32_t)(wn + 16 * p) * HROW_BYTES + so);
#pragma unroll
            for (int mi = 0; mi < 4; mi++)
#pragma unroll
                for (int ni = 0; ni < 4; ni++)
                    MMA_F16(c[mi][ni], af[mi], bf[ni]);
        }
        __syncthreads();
        if (++buf == 3) buf = 0;
    }

#pragma unroll
    for (int mi = 0; mi < 4; mi++) {
#pragma unroll
        for (int ni = 0; ni < 4; ni++) {
            int r  = row0 + wm + 16 * mi + lr;
            int cc = col0 + wn + 8 * ni + 2 * lk;
            if (Ch) {
                *(uint32_t*)&Ch[(size_t)r * N + cc]       = pk_h2(c[mi][ni][0], c[mi][ni][1]);
                *(uint32_t*)&Ch[(size_t)(r + 8) * N + cc] = pk_h2(c[mi][ni][2], c[mi][ni][3]);
            } else {
                Cf[(size_t)r * N + cc]           = c[mi][ni][0];
                Cf[(size_t)r * N + cc + 1]       = c[mi][ni][1];
                Cf[(size_t)(r + 8) * N + cc]     = c[mi][ni][2];
                Cf[(size_t)(r + 8) * N + cc + 1] = c[mi][ni][3];
            }
        }
    }
}

// ---------------------------------------------------------------------------
// RoPE on combined QKV buffer; folds (1/sqrt(HD))*log2e into Q.
// ---------------------------------------------------------------------------
__global__ __launch_bounds__(256) void rope_h_kernel(
    __half* __restrict__ qkv,
    const float* __restrict__ cosT, const float* __restrict__ sinT)
{
    const int bt  = blockIdx.x;
    const int t   = bt & (T_ - 1);
    const int tid = threadIdx.x;
    const float scale = 0.08838834764831845f * 1.4426950408889634f;
    const float* cr = cosT + (size_t)t * HD_;
    const float* sr = sinT + (size_t)t * HD_;

    __half* qrow = qkv + (size_t)bt * QKVN_;
    for (int p = tid; p < H_ * 64; p += 256) {
        int h = p >> 6, i = p & 63;
        __half* base = qrow + h * HD_;
        float q1 = __half2float(base[i]), q2 = __half2float(base[i + 64]);
        base[i]      = __float2half_rn((q1 * cr[i]      - q2 * sr[i]) * scale);
        base[i + 64] = __float2half_rn((q2 * cr[i + 64] + q1 * sr[i + 64]) * scale);
    }
    __half* krow = qrow + D_;
    for (int p = tid; p < HKV_ * 64; p += 256) {
        int h = p >> 6, i = p & 63;
        __half* base = krow + h * HD_;
        float k1 = __half2float(base[i]), k2 = __half2float(base[i + 64]);
        base[i]      = __float2half_rn(k1 * cr[i]      - k2 * sr[i]);
        base[i + 64] = __float2half_rn(k2 * cr[i + 64] + k1 * sr[i + 64]);
    }
}

// ---------------------------------------------------------------------------
// fp16 flash attention, BQ=64 / BK=64, 128 threads (4 warps), 2 CTAs/SM.
// Grid: (T/64, H, B). Warp w owns q-rows [w*16, w*16+16).
// Smem: two buffers of { Ks[64][68], Vs[64][68] } u32 words (34816 B each);
// total 69632 B -> two CTAs resident per SM (the point of this config).
// log2-domain softmax, f16x2 exp2, ones-MMA row sums, P in registers.
// ---------------------------------------------------------------------------
#define AT_TILE_WORDS 4352                    // 64 rows x 68 words
#define AT_BUF_WORDS (2 * AT_TILE_WORDS)      // Ks + Vs
#define AT_BUF_BYTES (AT_BUF_WORDS * 4)       // 34816
#define AT_VS_BOFF   (AT_TILE_WORDS * 4)      // 17408
#define ATTN_SMEM_BYTES (2 * AT_BUF_BYTES)    // 69632
#define KS_ROW_BYTES 272                      // 68 words

__global__ __launch_bounds__(128, 2) void attn_f16_kernel(
    const __half* __restrict__ qkv, __half* __restrict__ o)
{
    extern __shared__ uint32_t sw[];
    uint32_t* Qs = sw;                 // staging [64][68], aliases buffer 0

    const int qt  = (int)(gridDim.x - 1 - blockIdx.x);   // heavy tiles first
    const int h   = blockIdx.y;
    const int b   = blockIdx.z;
    const int kvh = h >> 2;
    const int q0  = qt * 64;
    const int tid  = threadIdx.x;
    const int lane = tid & 31;
    const int w    = tid >> 5;          // 0..3
    const int lr   = lane >> 2;
    const int lk   = lane & 3;

    const uint32_t smB = smem_u32(sw);
    const uint32_t brow   = (uint32_t)((lane >> 4) * 8 + (lane & 7));
    const uint32_t bcol16 = (uint32_t)((lane >> 3) & 1) * 16;
    const uint32_t arow   = (uint32_t)(lane & 15);
    const uint32_t asel16 = (uint32_t)(lane >> 4) * 16;

    // per-thread K/V load coords: 2 threads per key row, 64 halves (128 B) each
    const int krow = tid >> 1;          // key 0..63
    const int kd0  = (tid & 1) * 64;    // halves
    const uint32_t kvw = (uint32_t)(krow * 68 + (kd0 >> 1)) * 4;

    // ---- stage Q (log2e*scale pre-folded) and pull A-fragments ----
    {
        int row = tid >> 1;             // 0..63
        int d0  = (tid & 1) * 64;
        const __half* src = qkv + (size_t)(b * T_ + q0 + row) * QKVN_ + h * HD_ + d0;
#pragma unroll
        for (int j = 0; j < 64; j += 8)
            *(uint4*)&Qs[row * 68 + ((d0 + j) >> 1)] = *(const uint4*)(src + j);
    }
    __syncthreads();

    uint32_t aQ[8][4];
#pragma unroll
    for (int c = 0; c < 8; c++)
        LDSM_X4(aQ[c][0], aQ[c][1], aQ[c][2], aQ[c][3],
                smB + (uint32_t)(w * 16 + arow) * KS_ROW_BYTES
                    + (uint32_t)c * 32 + asel16);
    __syncthreads();

    float O[16][4];
#pragma unroll
    for (int nt = 0; nt < 16; nt++)
#pragma unroll
        for (int r = 0; r < 4; r++) O[nt][r] = 0.f;
    float m0 = -CUDART_INF_F, m1 = -CUDART_INF_F, l0 = 0.f, l1 = 0.f;

    const int row0g = q0 + w * 16 + lr;
    const int nkt = qt + 1;             // BK=64 tiles

    const __half* kbase = qkv + (size_t)(b * T_ + krow) * QKVN_ + D_ + kvh * HD_ + kd0;
    const __half* vbase = kbase + KVD_;

    // prologue: async-load tile 0 into buffer 0 (8 x 16B per thread per tensor)
#pragma unroll
    for (int j = 0; j < 8; j++) {
        CP_ASYNC16(smB + kvw + 16u * j,               kbase + 8 * j);
        CP_ASYNC16(smB + AT_VS_BOFF + kvw + 16u * j,  vbase + 8 * j);
    }
    CP_COMMIT();
    CP_WAIT0();
    __syncthreads();

    const uint32_t oneh2 = 0x3C003C00u;

    for (int kt = 0; kt < nkt; kt++) {
        const uint32_t bufB = smB + (uint32_t)(kt & 1) * AT_BUF_BYTES;

        if (kt + 1 < nkt) {
            const uint32_t nb = smB + (uint32_t)((kt + 1) & 1) * AT_BUF_BYTES;
            const size_t goff = (size_t)(kt + 1) * 64 * QKVN_;
#pragma unroll
            for (int j = 0; j < 8; j++) {
                CP_ASYNC16(nb + kvw + 16u * j,              kbase + goff + 8 * j);
                CP_ASYNC16(nb + AT_VS_BOFF + kvw + 16u * j, vbase + goff + 8 * j);
            }
            CP_COMMIT();
        }

        const int k0 = kt * 64;
        const bool active = (k0 <= q0 + w * 16 + 15);   // warp-uniform
        if (active) {
            const uint32_t KsB = bufB;
            const uint32_t VsB = bufB + AT_VS_BOFF;

            // ---- S = Q K^T (16 q-rows x 64 keys, log2 domain) ----
            float s[8][4];
#pragma unroll
            for (int nt = 0; nt < 8; nt++)
#pragma unroll
                for (int r = 0; r < 4; r++) s[nt][r] = 0.f;

#pragma unroll
            for (int c = 0; c < 8; c++) {
                uint32_t bf[8][2];
#pragma unroll
                for (int p = 0; p < 4; p++)
                    LDSM_X4(bf[2 * p][0], bf[2 * p][1], bf[2 * p + 1][0], bf[2 * p + 1][1],
                            KsB + (uint32_t)(p * 16 + brow) * KS_ROW_BYTES
                                + (uint32_t)c * 32 + bcol16);
#pragma unroll
                for (int nt = 0; nt < 8; nt++)
                    MMA_F16(s[nt], aQ[c], bf[nt]);
            }

            // ---- causal mask ----
            if (k0 + 63 > q0 + w * 16) {
#pragma unroll
                for (int nt = 0; nt < 8; nt++) {
                    int c0 = k0 + nt * 8 + 2 * lk;
                    if (c0     > row0g)     s[nt][0] = -CUDART_INF_F;
                    if (c0 + 1 > row0g)     s[nt][1] = -CUDART_INF_F;
                    if (c0     > row0g + 8) s[nt][2] = -CUDART_INF_F;
                    if (c0 + 1 > row0g + 8) s[nt][3] = -CUDART_INF_F;
                }
            }

            // ---- max + rescale (log2 domain) ----
            float mt0 = -CUDART_INF_F, mt1 = -CUDART_INF_F;
#pragma unroll
            for (int nt = 0; nt < 8; nt++) {
                mt0 = fmaxf(mt0, fmaxf(s[nt][0], s[nt][1]));
                mt1 = fmaxf(mt1, fmaxf(s[nt][2], s[nt][3]));
            }
#pragma unroll
            for (int off = 1; off <= 2; off <<= 1) {
                mt0 = fmaxf(mt0, __shfl_xor_sync(0xffffffffu, mt0, off));
                mt1 = fmaxf(mt1, __shfl_xor_sync(0xffffffffu, mt1, off));
            }
            float mn0 = fmaxf(m0, mt0), mn1 = fmaxf(m1, mt1);
            float al0 = exp2f(m0 - mn0), al1 = exp2f(m1 - mn1);
            m0 = mn0; m1 = mn1;
            l0 *= al0; l1 *= al1;
#pragma unroll
            for (int nt = 0; nt < 16; nt++) {
                O[nt][0] *= al0; O[nt][1] *= al0;
                O[nt][2] *= al1; O[nt][3] *= al1;
            }

            // ---- PV with f16x2 exp2; l via ones-MMA ----
            const half2 mh0 = __float2half2_rn(mn0);
            const half2 mh1 = __float2half2_rn(mn1);
            float lacc[4] = {0.f, 0.f, 0.f, 0.f};
            uint32_t ones[2] = { oneh2, oneh2 };
#pragma unroll
            for (int c = 0; c < 4; c++) {
                uint32_t pa[4];
                pa[0] = exp2_pair(s[2 * c][0],     s[2 * c][1],     mh0);
                pa[1] = exp2_pair(s[2 * c][2],     s[2 * c][3],     mh1);
                pa[2] = exp2_pair(s[2 * c + 1][0], s[2 * c + 1][1], mh0);
                pa[3] = exp2_pair(s[2 * c + 1][2], s[2 * c + 1][3], mh1);
                MMA_F16(lacc, pa, ones);
#pragma unroll
                for (int p = 0; p < 8; p++) {
                    uint32_t vb[2][2];
                    LDSM_X4_T(vb[0][0], vb[0][1], vb[1][0], vb[1][1],
                              VsB + (uint32_t)(c * 16 + arow) * KS_ROW_BYTES
                                  + (uint32_t)p * 32 + asel16);
                    MMA_F16(O[2 * p],     pa, vb[0]);
                    MMA_F16(O[2 * p + 1], pa, vb[1]);
                }
            }
            l0 += lacc[0];
            l1 += lacc[2];
        }

        if (kt + 1 < nkt) CP_WAIT0();
        __syncthreads();
    }

    // ---- epilogue (half out) ----
    float inv0 = 1.0f / l0, inv1 = 1.0f / l1;
    size_t r0base = (size_t)(b * T_ + q0 + w * 16 + lr) * D_ + h * HD_;
    size_t r1base = (size_t)(b * T_ + q0 + w * 16 + lr + 8) * D_ + h * HD_;
#pragma unroll
    for (int nt = 0; nt < 16; nt++) {
        *(uint32_t*)&o[r0base + nt * 8 + 2 * lk] = pk_h2(O[nt][0] * inv0, O[nt][1] * inv0);
        *(uint32_t*)&o[r1base + nt * 8 + 2 * lk] = pk_h2(O[nt][2] * inv1, O[nt][3] * inv1);
    }
}

// ---------------------------------------------------------------------------
// Launcher
// ---------------------------------------------------------------------------
extern "C" void kernel_launch(void* const* d_in, const int* in_sizes, int n_in,
                              void* d_out, int out_size)
{
    const float* x    = (const float*)d_in[0];
    const float* cosT = (const float*)d_in[1];
    const float* sinT = (const float*)d_in[2];
    const float* Wq   = (const float*)d_in[3];
    const float* Wk   = (const float*)d_in[4];
    const float* Wv   = (const float*)d_in[5];
    const float* Wo   = (const float*)d_in[6];
    float* out = (float*)d_out;

    __half *xh, *wqkvh, *woh, *gqkv, *gattn;
    cudaGetSymbolAddress((void**)&xh,    g_xh);
    cudaGetSymbolAddress((void**)&wqkvh, g_wqkvh);
    cudaGetSymbolAddress((void**)&woh,   g_woh);
    cudaGetSymbolAddress((void**)&gqkv,  g_qkv);
    cudaGetSymbolAddress((void**)&gattn, g_attn);

    cudaFuncSetAttribute(attn_f16_kernel, cudaFuncAttributeMaxDynamicSharedMemorySize,
                         ATTN_SMEM_BYTES);
    cudaFuncSetAttribute(gemm_nt_h_kernel,
                         cudaFuncAttributeMaxDynamicSharedMemorySize,
                         GEMM_SMEM_BYTES);

    dim3 blk(256);
    f2h_all_kernel<<<F2H_BLOCKS, blk>>>(x, Wq, Wk, Wv, Wo, xh, wqkvh, woh);

    dim3 qkv_grid(QKVN_ / 128, M_ / 128);   // 768 CTAs
    gemm_nt_h_kernel<<<qkv_grid, blk, GEMM_SMEM_BYTES>>>(xh, wqkvh, gqkv, nullptr,
                                                         M_, QKVN_, D_);

    rope_h_kernel<<<M_, blk>>>(gqkv, cosT, sinT);

    dim3 ga(T_ / 64, H_, B_);               // 32 x 16 x 2 = 1024 CTAs
    attn_f16_kernel<<<ga, dim3(128), ATTN_SMEM_BYTES>>>(gqkv, gattn);

    dim3 go_grid(D_ / 128, M_ / 128);
    gemm_nt_h_kernel<<<go_grid, blk, GEMM_SMEM_BYTES>>>(gattn, woh, nullptr, out,
                                                        M_, D_, D_);
}

// round 17
// speedup vs baseline: 1.0827x; 1.0827x over previous
#include <cuda_runtime.h>
#include <cuda_fp16.h>
#include <math_constants.h>
#include <stdint.h>

// Problem constants
#define B_   2
#define T_   2048
#define D_   2048
#define H_   16
#define HKV_ 4
#define HD_  128
#define G_   (H_ / HKV_)      // 4
#define M_   (B_ * T_)        // 4096
#define KVD_ (HKV_ * HD_)     // 512
#define QKVN_ (D_ + 2 * KVD_) // 3072

// ---------------------------------------------------------------------------
// Scratch (device globals; no allocation allowed)
// ---------------------------------------------------------------------------
__device__ __half g_xh[(size_t)M_ * D_];        // 16 MB
__device__ __half g_wqkvh[(size_t)QKVN_ * D_];  // 12 MB
__device__ __half g_woh[(size_t)D_ * D_];       //  8 MB
__device__ __half g_qkv[(size_t)M_ * QKVN_];    // 24 MB
__device__ __half g_attn[(size_t)M_ * D_];      // 16 MB (merged)
__device__ __half g_p0[(size_t)M_ * D_];        // 16 MB split partial 0
__device__ __half g_p1[(size_t)M_ * D_];        // 16 MB split partial 1
__device__ float2 g_st0[(size_t)M_ * H_];       // 0.5 MB (l, m)
__device__ float2 g_st1[(size_t)M_ * H_];       // 0.5 MB

// ---------------------------------------------------------------------------
// Helpers
// ---------------------------------------------------------------------------
__device__ __forceinline__ uint32_t pk_h2(float lo, float hi) {
    half2 h = __floats2half2_rn(lo, hi);
    return *(uint32_t*)&h;
}

__device__ __forceinline__ uint32_t smem_u32(const void* p) {
    uint32_t a;
    asm("{ .reg .u64 t; cvta.to.shared.u64 t, %1; cvt.u32.u64 %0, t; }"
        : "=r"(a) : "l"(p));
    return a;
}

__device__ __forceinline__ uint32_t exp2_pair(float lo, float hi, half2 mh) {
    half2 v = h2exp2(__hsub2(__floats2half2_rn(lo, hi), mh));
    return *(uint32_t*)&v;
}

#define MMA_F16(c, a, b)                                                      \
    asm volatile(                                                             \
        "mma.sync.aligned.m16n8k16.row.col.f32.f16.f16.f32 "                  \
        "{%0,%1,%2,%3},{%4,%5,%6,%7},{%8,%9},{%0,%1,%2,%3};"                  \
        : "+f"((c)[0]), "+f"((c)[1]), "+f"((c)[2]), "+f"((c)[3])              \
        : "r"((a)[0]), "r"((a)[1]), "r"((a)[2]), "r"((a)[3]),                 \
          "r"((b)[0]), "r"((b)[1]))

#define LDSM_X4(r0, r1, r2, r3, addr)                                         \
    asm volatile(                                                             \
        "ldmatrix.sync.aligned.m8n8.x4.shared.b16 {%0,%1,%2,%3}, [%4];"       \
        : "=r"(r0), "=r"(r1), "=r"(r2), "=r"(r3) : "r"(addr))

#define LDSM_X4_T(r0, r1, r2, r3, addr)                                       \
    asm volatile(                                                             \
        "ldmatrix.sync.aligned.m8n8.x4.trans.shared.b16 {%0,%1,%2,%3}, [%4];" \
        : "=r"(r0), "=r"(r1), "=r"(r2), "=r"(r3) : "r"(addr))

#define CP_ASYNC16(dst, src)                                                  \
    asm volatile("cp.async.cg.shared.global [%0], [%1], 16;"                  \
                 :: "r"(dst), "l"(src))
#define CP_COMMIT() asm volatile("cp.async.commit_group;" ::: "memory")
#define CP_WAIT0()  asm volatile("cp.async.wait_group 0;" ::: "memory")
#define CP_WAIT1()  asm volatile("cp.async.wait_group 1;" ::: "memory")

// ---------------------------------------------------------------------------
// Fused fp32->fp16 conversion (unchanged from R15)
// ---------------------------------------------------------------------------
#define XB_   (M_ * D_ / 2048)
#define WQB_  (D_ * D_ / 2048)
#define WKB_  (KVD_ * D_ / 2048)
#define WVB_  (KVD_ * D_ / 2048)
#define WOB_  (D_ * D_ / 2048)
#define F2H_BLOCKS (XB_ + WQB_ + WKB_ + WVB_ + WOB_)

__global__ __launch_bounds__(256) void f2h_all_kernel(
    const float* __restrict__ x,  const float* __restrict__ Wq,
    const float* __restrict__ Wk, const float* __restrict__ Wv,
    const float* __restrict__ Wo,
    __half* __restrict__ xh, __half* __restrict__ wqkvh,
    __half* __restrict__ woh)
{
    int blk = blockIdx.x;
    const float* src;
    __half* dst;
    if (blk < XB_)                     { src = x;  dst = xh;    }
    else if ((blk -= XB_)  < WQB_)     { src = Wq; dst = wqkvh; }
    else if ((blk -= WQB_) < WKB_)     { src = Wk; dst = wqkvh + (size_t)D_ * D_; }
    else if ((blk -= WKB_) < WVB_)     { src = Wv; dst = wqkvh + (size_t)(D_ + KVD_) * D_; }
    else { blk -= WVB_;                  src = Wo; dst = woh;   }

    size_t i = ((size_t)blk * 256 + threadIdx.x) * 8;
    float4 a = *(const float4*)(src + i);
    float4 b = *(const float4*)(src + i + 4);
    uint4 o = { pk_h2(a.x, a.y), pk_h2(a.z, a.w),
                pk_h2(b.x, b.y), pk_h2(b.z, b.w) };
    *(uint4*)(dst + i) = o;
}

// ---------------------------------------------------------------------------
// fp16 tensor-core GEMM, 3-stage cp.async pipeline (unchanged)
// ---------------------------------------------------------------------------
#define HSTRIDE 20
#define HROW_BYTES (HSTRIDE * 4)
#define HTILE_WORDS (128 * HSTRIDE)
#define HTILE_BYTES (HTILE_WORDS * 4)
#define GEMM_SMEM_BYTES (6 * HTILE_BYTES)

__global__ __launch_bounds__(256) void gemm_nt_h_kernel(
    const __half* __restrict__ A, const __half* __restrict__ Bm,
    __half* __restrict__ Ch, float* __restrict__ Cf, int M, int N, int K)
{
    extern __shared__ uint32_t smw[];
    const uint32_t smBase = smem_u32(smw);

    const int tid  = threadIdx.x;
    const int lane = tid & 31;
    const int warp = tid >> 5;
    const int row0 = blockIdx.y * 128;
    const int col0 = blockIdx.x * 128;
    const int wm   = (warp >> 2) * 64;
    const int wn   = (warp & 3) * 32;
    const int lk   = lane & 3;
    const int lr   = lane >> 2;

    const uint32_t aoff = (uint32_t)(lane & 15) * HROW_BYTES + (uint32_t)(lane >> 4) * 16;
    const uint32_t boff = ((uint32_t)((lane >> 4) * 8 + (lane & 7))) * HROW_BYTES
                        + (uint32_t)((lane >> 3) & 1) * 16;

    int mL[2], hcL[2];
    uint32_t stA[2], stB[2];
#pragma unroll
    for (int t = 0; t < 2; t++) {
        int idx = tid + 256 * t;
        mL[t]  = idx >> 2;
        hcL[t] = (idx & 3) << 3;
        uint32_t wb = (uint32_t)(mL[t] * HSTRIDE + ((idx & 3) << 2)) * 4;
        stA[t] = smBase + wb;
        stB[t] = smBase + 3 * HTILE_BYTES + wb;
    }

    float c[4][4][4];
#pragma unroll
    for (int mi = 0; mi < 4; mi++)
#pragma unroll
        for (int ni = 0; ni < 4; ni++)
#pragma unroll
            for (int r = 0; r < 4; r++) c[mi][ni][r] = 0.f;

    const int niter = K >> 5;

#pragma unroll
    for (int st = 0; st < 2; st++) {
        const int k0 = st << 5;
        const uint32_t bo = (uint32_t)st * HTILE_BYTES;
#pragma unroll
        for (int t = 0; t < 2; t++) {
            CP_ASYNC16(stA[t] + bo, &A [(size_t)(row0 + mL[t]) * K + k0 + hcL[t]]);
            CP_ASYNC16(stB[t] + bo, &Bm[(size_t)(col0 + mL[t]) * K + k0 + hcL[t]]);
        }
        CP_COMMIT();
    }

    int buf = 0;
    for (int it = 0; it < niter; ++it) {
        CP_WAIT1();
        __syncthreads();

        if (it + 2 < niter) {
            int nb = buf + 2; if (nb >= 3) nb -= 3;
            const int k0 = (it + 2) << 5;
            const uint32_t bo = (uint32_t)nb * HTILE_BYTES;
#pragma unroll
            for (int t = 0; t < 2; t++) {
                CP_ASYNC16(stA[t] + bo, &A [(size_t)(row0 + mL[t]) * K + k0 + hcL[t]]);
                CP_ASYNC16(stB[t] + bo, &Bm[(size_t)(col0 + mL[t]) * K + k0 + hcL[t]]);
            }
            CP_COMMIT();
        }

        const uint32_t aB = smBase + (uint32_t)buf * HTILE_BYTES + aoff;
        const uint32_t bB = smBase + (uint32_t)(3 + buf) * HTILE_BYTES + boff;
#pragma unroll
        for (int s = 0; s < 2; s++) {
            const uint32_t so = (uint32_t)s * 32;
            uint32_t af[4][4], bf[4][2];
#pragma unroll
            for (int mi = 0; mi < 4; mi++)
                LDSM_X4(af[mi][0], af[mi][1], af[mi][2], af[mi][3],
                        aB + (uint32_t)(wm + 16 * mi) * HROW_BYTES + so);
#pragma unroll
            for (int p = 0; p < 2; p++)
                LDSM_X4(bf[2 * p][0], bf[2 * p][1], bf[2 * p + 1][0], bf[2 * p + 1][1],
                        bB + (uint32_t)(wn + 16 * p) * HROW_BYTES + so);
#pragma unroll
            for (int mi = 0; mi < 4; mi++)
#pragma unroll
                for (int ni = 0; ni < 4; ni++)
                    MMA_F16(c[mi][ni], af[mi], bf[ni]);
        }
        __syncthreads();
        if (++buf == 3) buf = 0;
    }

#pragma unroll
    for (int mi = 0; mi < 4; mi++) {
#pragma unroll
        for (int ni = 0; ni < 4; ni++) {
            int r  = row0 + wm + 16 * mi + lr;
            int cc = col0 + wn + 8 * ni + 2 * lk;
            if (Ch) {
                *(uint32_t*)&Ch[(size_t)r * N + cc]       = pk_h2(c[mi][ni][0], c[mi][ni][1]);
                *(uint32_t*)&Ch[(size_t)(r + 8) * N + cc] = pk_h2(c[mi][ni][2], c[mi][ni][3]);
            } else {
                Cf[(size_t)r * N + cc]           = c[mi][ni][0];
                Cf[(size_t)r * N + cc + 1]       = c[mi][ni][1];
                Cf[(size_t)(r + 8) * N + cc]     = c[mi][ni][2];
                Cf[(size_t)(r + 8) * N + cc + 1] = c[mi][ni][3];
            }
        }
    }
}

// ---------------------------------------------------------------------------
// RoPE on combined QKV buffer; folds (1/sqrt(HD))*log2e into Q (unchanged)
// ---------------------------------------------------------------------------
__global__ __launch_bounds__(256) void rope_h_kernel(
    __half* __restrict__ qkv,
    const float* __restrict__ cosT, const float* __restrict__ sinT)
{
    const int bt  = blockIdx.x;
    const int t   = bt & (T_ - 1);
    const int tid = threadIdx.x;
    const float scale = 0.08838834764831845f * 1.4426950408889634f;
    const float* cr = cosT + (size_t)t * HD_;
    const float* sr = sinT + (size_t)t * HD_;

    __half* qrow = qkv + (size_t)bt * QKVN_;
    for (int p = tid; p < H_ * 64; p += 256) {
        int h = p >> 6, i = p & 63;
        __half* base = qrow + h * HD_;
        float q1 = __half2float(base[i]), q2 = __half2float(base[i + 64]);
        base[i]      = __float2half_rn((q1 * cr[i]      - q2 * sr[i]) * scale);
        base[i + 64] = __float2half_rn((q2 * cr[i + 64] + q1 * sr[i + 64]) * scale);
    }
    __half* krow = qrow + D_;
    for (int p = tid; p < HKV_ * 64; p += 256) {
        int h = p >> 6, i = p & 63;
        __half* base = krow + h * HD_;
        float k1 = __half2float(base[i]), k2 = __half2float(base[i + 64]);
        base[i]      = __float2half_rn(k1 * cr[i]      - k2 * sr[i]);
        base[i + 64] = __float2half_rn(k2 * cr[i + 64] + k1 * sr[i + 64]);
    }
}

// ---------------------------------------------------------------------------
// Split-K fp16 flash attention (R15 core, BQ=128/BK=128, 256 thr).
// Grid: (T/128, H, B*2); z = b*2+s. Split s handles half the kt range.
// Writes self-normalized partial + (l, m) stats; merge kernel combines.
// ---------------------------------------------------------------------------
#define AT_TILE_WORDS 8704
#define AT_BUF_WORDS (2 * AT_TILE_WORDS)
#define AT_BUF_BYTES (AT_BUF_WORDS * 4)       // 69632
#define AT_VS_BOFF   (AT_TILE_WORDS * 4)
#define ATTN_SMEM_BYTES (2 * AT_BUF_BYTES)    // 139264
#define KS_ROW_BYTES 272

__global__ __launch_bounds__(256, 1) void attn_f16_kernel(
    const __half* __restrict__ qkv,
    __half* __restrict__ p0, __half* __restrict__ p1,
    float2* __restrict__ st0, float2* __restrict__ st1)
{
    extern __shared__ uint32_t sw[];
    uint32_t* Qs = sw;

    const int qt  = (int)(gridDim.x - 1 - blockIdx.x);
    const int h   = blockIdx.y;
    const int b   = (int)(blockIdx.z >> 1);
    const int s   = (int)(blockIdx.z & 1);
    const int kvh = h >> 2;
    const int q0  = qt * 128;
    const int tid  = threadIdx.x;
    const int lane = tid & 31;
    const int w    = tid >> 5;
    const int lr   = lane >> 2;
    const int lk   = lane & 3;

    __half* part = s ? p1 : p0;
    float2* st   = s ? st1 : st0;

    const int nkt_tot = qt + 1;
    const int half = (nkt_tot + 1) >> 1;
    const int kt_lo = s ? half : 0;
    const int kt_hi = s ? nkt_tot : half;
    const int row0g = q0 + w * 16 + lr;

    if (kt_lo >= kt_hi) {               // empty split: zero-weight stats
        if (lk == 0) {
            st[(size_t)(b * T_ + row0g) * H_ + h]     = make_float2(0.f, -1e30f);
            st[(size_t)(b * T_ + row0g + 8) * H_ + h] = make_float2(0.f, -1e30f);
        }
        return;
    }

    const uint32_t smB = smem_u32(sw);
    const uint32_t brow   = (uint32_t)((lane >> 4) * 8 + (lane & 7));
    const uint32_t bcol16 = (uint32_t)((lane >> 3) & 1) * 16;
    const uint32_t arow   = (uint32_t)(lane & 15);
    const uint32_t asel16 = (uint32_t)(lane >> 4) * 16;

    const int krow = tid >> 1;
    const int kd0  = (tid & 1) * 64;
    const uint32_t kvw = (uint32_t)(krow * 68 + (kd0 >> 1)) * 4;

    // ---- stage Q ----
    {
        int row = tid >> 1;
        int d0  = (tid & 1) * 64;
        const __half* src = qkv + (size_t)(b * T_ + q0 + row) * QKVN_ + h * HD_ + d0;
#pragma unroll
        for (int j = 0; j < 64; j += 8)
            *(uint4*)&Qs[row * 68 + ((d0 + j) >> 1)] = *(const uint4*)(src + j);
    }
    __syncthreads();

    uint32_t aQ[8][4];
#pragma unroll
    for (int c = 0; c < 8; c++)
        LDSM_X4(aQ[c][0], aQ[c][1], aQ[c][2], aQ[c][3],
                smB + (uint32_t)(w * 16 + arow) * KS_ROW_BYTES
                    + (uint32_t)c * 32 + asel16);
    __syncthreads();

    float O[16][4];
#pragma unroll
    for (int nt = 0; nt < 16; nt++)
#pragma unroll
        for (int r = 0; r < 4; r++) O[nt][r] = 0.f;
    float m0 = -CUDART_INF_F, m1 = -CUDART_INF_F, l0 = 0.f, l1 = 0.f;

    const __half* kbase = qkv + (size_t)(b * T_ + kt_lo * 128 + krow) * QKVN_ + D_
                        + kvh * HD_ + kd0;
    const __half* vbase = kbase + KVD_;
    const int nkt = kt_hi - kt_lo;

    // prologue
#pragma unroll
    for (int j = 0; j < 8; j++) {
        CP_ASYNC16(smB + kvw + 16u * j,               kbase + 8 * j);
        CP_ASYNC16(smB + AT_VS_BOFF + kvw + 16u * j,  vbase + 8 * j);
    }
    CP_COMMIT();
    CP_WAIT0();
    __syncthreads();

    const uint32_t oneh2 = 0x3C003C00u;

    for (int kl = 0; kl < nkt; kl++) {
        const uint32_t bufB = smB + (uint32_t)(kl & 1) * AT_BUF_BYTES;

        if (kl + 1 < nkt) {
            const uint32_t nb = smB + (uint32_t)((kl + 1) & 1) * AT_BUF_BYTES;
            const size_t goff = (size_t)(kl + 1) * 128 * QKVN_;
#pragma unroll
            for (int j = 0; j < 8; j++) {
                CP_ASYNC16(nb + kvw + 16u * j,              kbase + goff + 8 * j);
                CP_ASYNC16(nb + AT_VS_BOFF + kvw + 16u * j, vbase + goff + 8 * j);
            }
            CP_COMMIT();
        }

        const int k0 = (kt_lo + kl) * 128;
        const bool active = (k0 <= q0 + w * 16 + 15);
        if (active) {
            const uint32_t KsB = bufB;
            const uint32_t VsB = bufB + AT_VS_BOFF;

            float sc[16][4];
#pragma unroll
            for (int nt = 0; nt < 16; nt++)
#pragma unroll
                for (int r = 0; r < 4; r++) sc[nt][r] = 0.f;

#pragma unroll
            for (int c = 0; c < 8; c++) {
                uint32_t bf[16][2];
#pragma unroll
                for (int p = 0; p < 8; p++)
                    LDSM_X4(bf[2 * p][0], bf[2 * p][1], bf[2 * p + 1][0], bf[2 * p + 1][1],
                            KsB + (uint32_t)(p * 16 + brow) * KS_ROW_BYTES
                                + (uint32_t)c * 32 + bcol16);
#pragma unroll
                for (int nt = 0; nt < 16; nt++)
                    MMA_F16(sc[nt], aQ[c], bf[nt]);
            }

            if (k0 + 127 > q0 + w * 16) {
#pragma unroll
                for (int nt = 0; nt < 16; nt++) {
                    int c0 = k0 + nt * 8 + 2 * lk;
                    if (c0     > row0g)     sc[nt][0] = -CUDART_INF_F;
                    if (c0 + 1 > row0g)     sc[nt][1] = -CUDART_INF_F;
                    if (c0     > row0g + 8) sc[nt][2] = -CUDART_INF_F;
                    if (c0 + 1 > row0g + 8) sc[nt][3] = -CUDART_INF_F;
                }
            }

            float mt0 = -CUDART_INF_F, mt1 = -CUDART_INF_F;
#pragma unroll
            for (int nt = 0; nt < 16; nt++) {
                mt0 = fmaxf(mt0, fmaxf(sc[nt][0], sc[nt][1]));
                mt1 = fmaxf(mt1, fmaxf(sc[nt][2], sc[nt][3]));
            }
#pragma unroll
            for (int off = 1; off <= 2; off <<= 1) {
                mt0 = fmaxf(mt0, __shfl_xor_sync(0xffffffffu, mt0, off));
                mt1 = fmaxf(mt1, __shfl_xor_sync(0xffffffffu, mt1, off));
            }
            float mn0 = fmaxf(m0, mt0), mn1 = fmaxf(m1, mt1);
            float al0 = exp2f(m0 - mn0), al1 = exp2f(m1 - mn1);
            m0 = mn0; m1 = mn1;
            l0 *= al0; l1 *= al1;
#pragma unroll
            for (int nt = 0; nt < 16; nt++) {
                O[nt][0] *= al0; O[nt][1] *= al0;
                O[nt][2] *= al1; O[nt][3] *= al1;
            }

            const half2 mh0 = __float2half2_rn(mn0);
            const half2 mh1 = __float2half2_rn(mn1);
            float lacc[4] = {0.f, 0.f, 0.f, 0.f};
            uint32_t ones[2] = { oneh2, oneh2 };
#pragma unroll
            for (int c = 0; c < 8; c++) {
                uint32_t pa[4];
                pa[0] = exp2_pair(sc[2 * c][0],     sc[2 * c][1],     mh0);
                pa[1] = exp2_pair(sc[2 * c][2],     sc[2 * c][3],     mh1);
                pa[2] = exp2_pair(sc[2 * c + 1][0], sc[2 * c + 1][1], mh0);
                pa[3] = exp2_pair(sc[2 * c + 1][2], sc[2 * c + 1][3], mh1);
                MMA_F16(lacc, pa, ones);
#pragma unroll
                for (int p = 0; p < 8; p++) {
                    uint32_t vb[2][2];
                    LDSM_X4_T(vb[0][0], vb[0][1], vb[1][0], vb[1][1],
                              VsB + (uint32_t)(c * 16 + arow) * KS_ROW_BYTES
                                  + (uint32_t)p * 32 + asel16);
                    MMA_F16(O[2 * p],     pa, vb[0]);
                    MMA_F16(O[2 * p + 1], pa, vb[1]);
                }
            }
            l0 += lacc[0];
            l1 += lacc[2];
        }

        if (kl + 1 < nkt) CP_WAIT0();
        __syncthreads();
    }

    // ---- epilogue: self-normalized partial + stats ----
    float inv0 = (l0 > 0.f) ? 1.0f / l0 : 0.f;
    float inv1 = (l1 > 0.f) ? 1.0f / l1 : 0.f;
    size_t r0base = (size_t)(b * T_ + q0 + w * 16 + lr) * D_ + h * HD_;
    size_t r1base = (size_t)(b * T_ + q0 + w * 16 + lr + 8) * D_ + h * HD_;
#pragma unroll
    for (int nt = 0; nt < 16; nt++) {
        *(uint32_t*)&part[r0base + nt * 8 + 2 * lk] = pk_h2(O[nt][0] * inv0, O[nt][1] * inv0);
        *(uint32_t*)&part[r1base + nt * 8 + 2 * lk] = pk_h2(O[nt][2] * inv1, O[nt][3] * inv1);
    }
    if (lk == 0) {
        st[(size_t)(b * T_ + row0g) * H_ + h]     = make_float2(l0, m0);
        st[(size_t)(b * T_ + row0g + 8) * H_ + h] = make_float2(l1, m1);
    }
}

// ---------------------------------------------------------------------------
// Merge the two split partials: out = (w0*P0 + w1*P1)/(w0+w1), w_s = l_s*2^(m_s-m)
// Grid: M_ blocks x 256 threads (8 halves each).
// ---------------------------------------------------------------------------
__global__ __launch_bounds__(256) void attn_merge_kernel(
    const __half* __restrict__ p0, const __half* __restrict__ p1,
    const float2* __restrict__ st0, const float2* __restrict__ st1,
    __half* __restrict__ out)
{
    const int row = blockIdx.x;
    const int tid = threadIdx.x;
    const int col = tid * 8;
    const int h   = col >> 7;

    float2 s0 = st0[(size_t)row * H_ + h];
    float2 s1 = st1[(size_t)row * H_ + h];
    float m  = fmaxf(s0.y, s1.y);
    float w0 = s0.x * exp2f(s0.y - m);
    float w1 = s1.x * exp2f(s1.y - m);
    float inv = 1.0f / (w0 + w1);
    w0 *= inv; w1 *= inv;

    size_t base = (size_t)row * D_ + col;
    uint4 a = *(const uint4*)(p0 + base);
    uint4 bqv = *(const uint4*)(p1 + base);
    const __half* ah = (const __half*)&a;
    const __half* bh = (const __half*)&bqv;
    uint4 o;
    __half* oh = (__half*)&o;
#pragma unroll
    for (int j = 0; j < 8; j++)
        oh[j] = __float2half_rn(w0 * __half2float(ah[j]) + w1 * __half2float(bh[j]));
    *(uint4*)(out + base) = o;
}

// ---------------------------------------------------------------------------
// Launcher
// ---------------------------------------------------------------------------
extern "C" void kernel_launch(void* const* d_in, const int* in_sizes, int n_in,
                              void* d_out, int out_size)
{
    const float* x    = (const float*)d_in[0];
    const float* cosT = (const float*)d_in[1];
    const float* sinT = (const float*)d_in[2];
    const float* Wq   = (const float*)d_in[3];
    const float* Wk   = (const float*)d_in[4];
    const float* Wv   = (const float*)d_in[5];
    const float* Wo   = (const float*)d_in[6];
    float* out = (float*)d_out;

    __half *xh, *wqkvh, *woh, *gqkv, *gattn, *gp0, *gp1;
    float2 *gst0, *gst1;
    cudaGetSymbolAddress((void**)&xh,    g_xh);
    cudaGetSymbolAddress((void**)&wqkvh, g_wqkvh);
    cudaGetSymbolAddress((void**)&woh,   g_woh);
    cudaGetSymbolAddress((void**)&gqkv,  g_qkv);
    cudaGetSymbolAddress((void**)&gattn, g_attn);
    cudaGetSymbolAddress((void**)&gp0,   g_p0);
    cudaGetSymbolAddress((void**)&gp1,   g_p1);
    cudaGetSymbolAddress((void**)&gst0,  g_st0);
    cudaGetSymbolAddress((void**)&gst1,  g_st1);

    cudaFuncSetAttribute(attn_f16_kernel, cudaFuncAttributeMaxDynamicSharedMemorySize,
                         ATTN_SMEM_BYTES);
    cudaFuncSetAttribute(gemm_nt_h_kernel,
                         cudaFuncAttributeMaxDynamicSharedMemorySize,
                         GEMM_SMEM_BYTES);

    dim3 blk(256);
    f2h_all_kernel<<<F2H_BLOCKS, blk>>>(x, Wq, Wk, Wv, Wo, xh, wqkvh, woh);

    dim3 qkv_grid(QKVN_ / 128, M_ / 128);
    gemm_nt_h_kernel<<<qkv_grid, blk, GEMM_SMEM_BYTES>>>(xh, wqkvh, gqkv, nullptr,
                                                         M_, QKVN_, D_);

    rope_h_kernel<<<M_, blk>>>(gqkv, cosT, sinT);

    dim3 ga(T_ / 128, H_, B_ * 2);          // 16 x 16 x 4 = 1024 CTAs (split-K)
    attn_f16_kernel<<<ga, blk, ATTN_SMEM_BYTES>>>(gqkv, gp0, gp1, gst0, gst1);

    attn_merge_kernel<<<M_, blk>>>(gp0, gp1, gst0, gst1, gattn);

    dim3 go_grid(D_ / 128, M_ / 128);
    gemm_nt_h_kernel<<<go_grid, blk, GEMM_SMEM_BYTES>>>(gattn, woh, nullptr, out,
                                                        M_, D_, D_);
}